// round 10
// baseline (speedup 1.0000x reference)
#include <cuda_runtime.h>
#include <cuda_bf16.h>
#include <math.h>
#include <stdint.h>

#define B_   128
#define S_   1000
#define H_   256
#define M_   (B_ * S_)   // 128000

// ---------------- scratch (__device__ globals; no allocation allowed) ----------
__device__ float g_ce[B_ * H_];
__device__ float g_ct[B_ * H_];
__device__ float g_cs[B_ * H_];
__device__ float g_gi[B_ * 3 * H_];       // dec @ Wih^T
__device__ float g_gh[B_ * 3 * H_];       // lasth @ Whh^T
__device__ float g_hnew[B_ * H_];
__device__ float g_scores[2 * M_];        // softmaxed attention (enc, tgt)
__device__ float g_sp[2][2 * M_];         // raw score partials per n-half
__device__ float g_fp[2][M_];             // final prob partials per n-half
__device__ float g_ctx[2 * B_ * H_];      // enc ctx, tgt ctx
__device__ float g_d[2 * B_ * H_];        // d_e, d_t
// bf16 hi/lo splits
__device__ __nv_bfloat16 g_Xhi[(size_t)M_ * H_];
__device__ __nv_bfloat16 g_Xlo[(size_t)M_ * H_];
__device__ __nv_bfloat16 g_Whi[768 * H_];   // stacked [Wenc1; Wtgt1; Wptr1] cols [0,H)
__device__ __nv_bfloat16 g_Wlo[768 * H_];

// =================== mma.sync / ldmatrix / cp.async helpers ====================
__device__ __forceinline__ uint32_t s2u(const void* p) {
    uint32_t a;
    asm("{ .reg .u64 t; cvta.to.shared.u64 t, %1; cvt.u32.u64 %0, t; }" : "=r"(a) : "l"(p));
    return a;
}
__device__ __forceinline__ void ldsm4(uint32_t& r0, uint32_t& r1, uint32_t& r2, uint32_t& r3,
                                      uint32_t addr) {
    asm volatile("ldmatrix.sync.aligned.m8n8.x4.shared.b16 {%0,%1,%2,%3}, [%4];"
                 : "=r"(r0), "=r"(r1), "=r"(r2), "=r"(r3) : "r"(addr));
}
__device__ __forceinline__ void ldsm2(uint32_t& r0, uint32_t& r1, uint32_t addr) {
    asm volatile("ldmatrix.sync.aligned.m8n8.x2.shared.b16 {%0,%1}, [%2];"
                 : "=r"(r0), "=r"(r1) : "r"(addr));
}
__device__ __forceinline__ void mma16816(float& d0, float& d1, float& d2, float& d3,
                                         uint32_t a0, uint32_t a1, uint32_t a2, uint32_t a3,
                                         uint32_t b0, uint32_t b1) {
    asm volatile("mma.sync.aligned.m16n8k16.row.col.f32.bf16.bf16.f32 "
                 "{%0,%1,%2,%3}, {%4,%5,%6,%7}, {%8,%9}, {%0,%1,%2,%3};"
                 : "+f"(d0), "+f"(d1), "+f"(d2), "+f"(d3)
                 : "r"(a0), "r"(a1), "r"(a2), "r"(a3), "r"(b0), "r"(b1));
}
__device__ __forceinline__ void cpa16(uint32_t dst, const void* src) {
    asm volatile("cp.async.cg.shared.global [%0], [%1], 16;" :: "r"(dst), "l"(src));
}
__device__ __forceinline__ void cpa_commit() {
    asm volatile("cp.async.commit_group;" ::: "memory");
}

// ---------------- zero ctx accumulators ----------------------------------------
__global__ void zero_ctx() {
    int i = blockIdx.x * blockDim.x + threadIdx.x;
    if (i < 2 * B_ * H_) g_ctx[i] = 0.0f;
}

// ---------------- prepass: fp32 -> bf16 hi/lo splits ----------------------------
__device__ __forceinline__ void split8(const float* __restrict__ src,
                                       __nv_bfloat16* __restrict__ hi,
                                       __nv_bfloat16* __restrict__ lo) {
    float4 x0 = *(const float4*)src;
    float4 x1 = *(const float4*)(src + 4);
    float v[8] = {x0.x, x0.y, x0.z, x0.w, x1.x, x1.y, x1.z, x1.w};
    __nv_bfloat16 h[8], l[8];
    #pragma unroll
    for (int i = 0; i < 8; ++i) {
        h[i] = __float2bfloat16(v[i]);
        l[i] = __float2bfloat16(v[i] - __bfloat162float(h[i]));
    }
    *(uint4*)hi = *(uint4*)h;
    *(uint4*)lo = *(uint4*)l;
}

__global__ void conv_x(const float* __restrict__ X) {
    size_t g = (size_t)blockIdx.x * blockDim.x + threadIdx.x;   // 4,096,000 groups
    split8(X + g * 8, g_Xhi + g * 8, g_Xlo + g * 8);
}

__global__ void conv_w(const float* __restrict__ Wenc,
                       const float* __restrict__ Wtgt,
                       const float* __restrict__ Wptr) {
    int g = blockIdx.x * blockDim.x + threadIdx.x;   // 24576 groups
    int row = g >> 5, c8 = g & 31;
    const float* src;
    if (row < 256)      src = Wenc + (size_t)row * (2 * H_) + c8 * 8;
    else if (row < 512) src = Wtgt + (size_t)(row - 256) * (2 * H_) + c8 * 8;
    else                src = Wptr + (size_t)(row - 512) * (3 * H_) + c8 * 8;
    split8(src, g_Whi + (size_t)row * H_ + c8 * 8, g_Wlo + (size_t)row * H_ + c8 * 8);
}

// ---------------- small fp32 GEMM: C[M,N] = A[M,256] @ W[N,256]^T ---------------
__device__ __forceinline__ void gemm64_body(const float* __restrict__ A,
                                            const float* __restrict__ W, int wstride,
                                            float* __restrict__ C, int ldc,
                                            int m0, int n0) {
    __shared__ float As[32][64];
    __shared__ float Bs[32][64];
    const int tid = threadIdx.x;
    const int lm = tid & 63;
    const int lq = tid >> 6;
    const int tn = tid & 15;
    const int tm = tid >> 4;

    float acc[4][4];
    #pragma unroll
    for (int i = 0; i < 4; ++i)
        #pragma unroll
        for (int j = 0; j < 4; ++j) acc[i][j] = 0.f;

    const float* arow = A + (size_t)(m0 + lm) * 256;
    const float* wrow = W + (size_t)(n0 + lm) * wstride;

    for (int kt = 0; kt < 8; ++kt) {
        const int k0 = kt * 32;
        #pragma unroll
        for (int h = 0; h < 2; ++h) {
            const int kk = (lq + h * 4) * 4;
            float4 xa = *(const float4*)(arow + k0 + kk);
            As[kk + 0][lm] = xa.x; As[kk + 1][lm] = xa.y;
            As[kk + 2][lm] = xa.z; As[kk + 3][lm] = xa.w;
            float4 wa = *(const float4*)(wrow + k0 + kk);
            Bs[kk + 0][lm] = wa.x; Bs[kk + 1][lm] = wa.y;
            Bs[kk + 2][lm] = wa.z; Bs[kk + 3][lm] = wa.w;
        }
        __syncthreads();
        #pragma unroll
        for (int k = 0; k < 32; ++k) {
            float4 a = *(const float4*)&As[k][tm * 4];
            float4 b = *(const float4*)&Bs[k][tn * 4];
            acc[0][0] += a.x * b.x; acc[0][1] += a.x * b.y; acc[0][2] += a.x * b.z; acc[0][3] += a.x * b.w;
            acc[1][0] += a.y * b.x; acc[1][1] += a.y * b.y; acc[1][2] += a.y * b.z; acc[1][3] += a.y * b.w;
            acc[2][0] += a.z * b.x; acc[2][1] += a.z * b.y; acc[2][2] += a.z * b.z; acc[2][3] += a.z * b.w;
            acc[3][0] += a.w * b.x; acc[3][1] += a.w * b.y; acc[3][2] += a.w * b.z; acc[3][3] += a.w * b.w;
        }
        __syncthreads();
    }
    #pragma unroll
    for (int i = 0; i < 4; ++i) {
        float4 o = make_float4(acc[i][0], acc[i][1], acc[i][2], acc[i][3]);
        *(float4*)(C + (size_t)(m0 + tm * 4 + i) * ldc + n0 + tn * 4) = o;
    }
}

__global__ void __launch_bounds__(256) gemm_gigh(const float* __restrict__ dec,
                                                 const float* __restrict__ lasth,
                                                 const float* __restrict__ Wih,
                                                 const float* __restrict__ Whh) {
    const int z = blockIdx.z;
    gemm64_body(z == 0 ? dec : lasth, z == 0 ? Wih : Whh, 256,
                z == 0 ? g_gi : g_gh, 768, blockIdx.x * 64, blockIdx.y * 64);
}

__global__ void gru_elem(const float* __restrict__ lasth,
                         const float* __restrict__ bih,
                         const float* __restrict__ bhh,
                         float* __restrict__ out_h) {
    const int b = blockIdx.x, t = threadIdx.x;
    const float gir = g_gi[b * 768 + t] + bih[t];
    const float giz = g_gi[b * 768 + t + H_] + bih[t + H_];
    const float gig = g_gi[b * 768 + t + 2 * H_] + bih[t + 2 * H_];
    const float ghr = g_gh[b * 768 + t] + bhh[t];
    const float ghz = g_gh[b * 768 + t + H_] + bhh[t + H_];
    const float ghg = g_gh[b * 768 + t + 2 * H_] + bhh[t + 2 * H_];
    const float r = 1.0f / (1.0f + expf(-(gir + ghr)));
    const float z = 1.0f / (1.0f + expf(-(giz + ghz)));
    const float n = tanhf(gig + r * ghg);
    const float hn = (1.0f - z) * n + z * lasth[b * H_ + t];
    g_hnew[b * H_ + t] = hn;
    out_h[b * H_ + t] = hn;
}

__global__ void __launch_bounds__(256) gemm_c(const float* __restrict__ tgt,
                                              const float* __restrict__ semb,
                                              const float* __restrict__ Wenc,
                                              const float* __restrict__ Wtgt,
                                              const float* __restrict__ Wptr) {
    const int z = blockIdx.z;
    const float* A;
    const float* W;
    int ws;
    float* C;
    if (z == 0)      { A = g_hnew; W = Wenc + H_;     ws = 2 * H_; C = g_ce; }
    else if (z == 1) { A = tgt;    W = Wtgt + H_;     ws = 2 * H_; C = g_ct; }
    else             { A = semb;   W = Wptr + 2 * H_; ws = 3 * H_; C = g_cs; }
    gemm64_body(A, W, ws, C, 256, blockIdx.x * 64, blockIdx.y * 64);
}

// ---------------- big bf16-split tensor-core GEMM mainloop ---------------------
// CTA: 128(M) x 128(N), K=256 in 8 chunks of 32. ALL four operand buffers
// (A-hi, A-lo, B-hi, B-lo) stream via double-buffered cp.async from the
// pre-split bf16 arrays. Mainloop is pure cp.async + ldsm + mma.
#define PADB   80                 // smem row stride bytes (64B data + 16 pad)
#define BUFSZ  10240              // one operand buffer (128 rows x PADB)
#define STAGEB (4 * BUFSZ)        // 40960
#define SMTOT  (2 * STAGEB)       // 81920 bytes dynamic smem

__device__ __forceinline__ void mainloop128(float (&acc)[4][4][4],
                                            int m0, int wrow0, uint32_t sb) {
    const int tid = threadIdx.x;
    const int lane = tid & 31, wid = tid >> 5;
    const int warp_m = wid & 1, warp_n = wid >> 1;

    #pragma unroll
    for (int i = 0; i < 4; ++i)
        #pragma unroll
        for (int j = 0; j < 4; ++j)
            #pragma unroll
            for (int k = 0; k < 4; ++k) acc[i][j][k] = 0.f;

    const uint32_t aOff = (uint32_t)((warp_m * 64 + (lane & 15)) * PADB + (lane >> 4) * 16);
    const uint32_t bOff = (uint32_t)((warp_n * 32 + (lane & 7)) * PADB + ((lane >> 3) & 1) * 16);

    // cp.async mapping: q = 0..7; buf = q>>1; row = (tid>>2) + (q&1)*64; c = tid&3
    const int rlo = tid >> 2;
    const int c16 = (tid & 3) * 16;
    const int coff = (tid & 3) * 8;
    const __nv_bfloat16* base0 = g_Xhi + (size_t)m0 * H_;
    const __nv_bfloat16* base1 = g_Xlo + (size_t)m0 * H_;
    const __nv_bfloat16* base2 = g_Whi + (size_t)wrow0 * H_;
    const __nv_bfloat16* base3 = g_Wlo + (size_t)wrow0 * H_;

    #define FILL(stg, kc_)                                                          \
    {                                                                               \
        const int k0 = (kc_) * 32;                                                  \
        const uint32_t d0 = (uint32_t)(stg) + (uint32_t)(rlo * PADB + c16);         \
        const uint32_t d1 = d0 + 64 * PADB;                                         \
        cpa16(sb + d0,              base0 + (size_t)rlo * H_ + k0 + coff);          \
        cpa16(sb + d1,              base0 + (size_t)(rlo + 64) * H_ + k0 + coff);   \
        cpa16(sb + d0 + BUFSZ,      base1 + (size_t)rlo * H_ + k0 + coff);          \
        cpa16(sb + d1 + BUFSZ,      base1 + (size_t)(rlo + 64) * H_ + k0 + coff);   \
        cpa16(sb + d0 + 2 * BUFSZ,  base2 + (size_t)rlo * H_ + k0 + coff);          \
        cpa16(sb + d1 + 2 * BUFSZ,  base2 + (size_t)(rlo + 64) * H_ + k0 + coff);   \
        cpa16(sb + d0 + 3 * BUFSZ,  base3 + (size_t)rlo * H_ + k0 + coff);          \
        cpa16(sb + d1 + 3 * BUFSZ,  base3 + (size_t)(rlo + 64) * H_ + k0 + coff);   \
        cpa_commit();                                                               \
    }

    FILL(0, 0);

    for (int kc = 0; kc < 8; ++kc) {
        const uint32_t so = (uint32_t)((kc & 1) * STAGEB);
        if (kc < 7) {
            const uint32_t sn = (uint32_t)(((kc + 1) & 1) * STAGEB);
            FILL(sn, kc + 1);
            asm volatile("cp.async.wait_group 1;" ::: "memory");
        } else {
            asm volatile("cp.async.wait_group 0;" ::: "memory");
        }
        __syncthreads();
        #pragma unroll
        for (int ks = 0; ks < 2; ++ks) {
            const uint32_t kb = ks * 32;
            uint32_t ah[4][4], al[4][4], bh[4][2], bl[4][2];
            #pragma unroll
            for (int i = 0; i < 4; ++i)
                ldsm4(ah[i][0], ah[i][1], ah[i][2], ah[i][3],
                      sb + so + aOff + i * (16 * PADB) + kb);
            #pragma unroll
            for (int j = 0; j < 4; ++j)
                ldsm2(bh[j][0], bh[j][1], sb + so + 2 * BUFSZ + bOff + j * (8 * PADB) + kb);
            #pragma unroll
            for (int i = 0; i < 4; ++i)
                #pragma unroll
                for (int j = 0; j < 4; ++j)
                    mma16816(acc[i][j][0], acc[i][j][1], acc[i][j][2], acc[i][j][3],
                             ah[i][0], ah[i][1], ah[i][2], ah[i][3], bh[j][0], bh[j][1]);
            #pragma unroll
            for (int j = 0; j < 4; ++j)
                ldsm2(bl[j][0], bl[j][1], sb + so + 3 * BUFSZ + bOff + j * (8 * PADB) + kb);
            #pragma unroll
            for (int i = 0; i < 4; ++i)
                #pragma unroll
                for (int j = 0; j < 4; ++j)
                    mma16816(acc[i][j][0], acc[i][j][1], acc[i][j][2], acc[i][j][3],
                             ah[i][0], ah[i][1], ah[i][2], ah[i][3], bl[j][0], bl[j][1]);
            #pragma unroll
            for (int i = 0; i < 4; ++i)
                ldsm4(al[i][0], al[i][1], al[i][2], al[i][3],
                      sb + so + BUFSZ + aOff + i * (16 * PADB) + kb);
            #pragma unroll
            for (int i = 0; i < 4; ++i)
                #pragma unroll
                for (int j = 0; j < 4; ++j)
                    mma16816(acc[i][j][0], acc[i][j][1], acc[i][j][2], acc[i][j][3],
                             al[i][0], al[i][1], al[i][2], al[i][3], bh[j][0], bh[j][1]);
        }
        __syncthreads();
    }
    #undef FILL
}

// ---------------- scores GEMM (enc/tgt) with fused v.tanh reduction ------------
__global__ void __launch_bounds__(256, 2) gemm_scores(const float* __restrict__ v_enc,
                                                      const float* __restrict__ v_tgt) {
    extern __shared__ char smem[];
    const uint32_t sb = s2u(smem);
    const int tid = threadIdx.x;
    const int lane = tid & 31, wid = tid >> 5;
    const int warp_m = wid & 1, warp_n = wid >> 1;
    const int m0 = blockIdx.y * 128;
    const int grp = blockIdx.x >> 1;           // 0=enc, 1=tgt
    const int half = blockIdx.x & 1;
    const int n0 = half * 128;
    const int wrow0 = grp * 256 + n0;

    float acc[4][4][4];
    mainloop128(acc, m0, wrow0, sb);

    float (*red)[4] = (float(*)[4])smem;       // alias stage0 (safe post-sync)
    const int mw = warp_m * 64, nw = warp_n * 32;
    const float* v = (grp == 0) ? v_enc : v_tgt;
    const float* cb = (grp == 0) ? g_ce : g_ct;
    #pragma unroll
    for (int i = 0; i < 4; ++i) {
        #pragma unroll
        for (int r = 0; r < 2; ++r) {
            const int row = mw + i * 16 + r * 8 + (lane >> 2);
            const int b = (m0 + row) / S_;
            const float* cbb = cb + b * H_;
            float p = 0.f;
            #pragma unroll
            for (int j = 0; j < 4; ++j) {
                const int n = n0 + nw + j * 8 + (lane & 3) * 2;
                p += __ldg(v + n) * tanhf(acc[i][j][r * 2] + __ldg(cbb + n));
                p += __ldg(v + n + 1) * tanhf(acc[i][j][r * 2 + 1] + __ldg(cbb + n + 1));
            }
            p += __shfl_xor_sync(0xffffffffu, p, 1);
            p += __shfl_xor_sync(0xffffffffu, p, 2);
            if ((lane & 3) == 0) red[row][warp_n] = p;
        }
    }
    __syncthreads();
    if (tid < 128) {
        const float s = red[tid][0] + red[tid][1] + red[tid][2] + red[tid][3];
        g_sp[half][grp * M_ + m0 + tid] = s;
    }
}

// ---------------- final GEMM (ptr) with fused prob epilogue --------------------
__global__ void __launch_bounds__(256, 2) gemm_final(const float* __restrict__ v_ptr) {
    extern __shared__ char smem[];
    const uint32_t sb = s2u(smem);
    const int tid = threadIdx.x;
    const int lane = tid & 31, wid = tid >> 5;
    const int warp_m = wid & 1, warp_n = wid >> 1;
    const int m0 = blockIdx.y * 128;
    const int half = blockIdx.x;
    const int n0 = half * 128;
    const int wrow0 = 512 + n0;

    float acc[4][4][4];
    mainloop128(acc, m0, wrow0, sb);

    float (*redE)[4] = (float(*)[4])smem;
    float (*redT)[4] = (float(*)[4])(smem + 2048);
    const int mw = warp_m * 64, nw = warp_n * 32;
    #pragma unroll
    for (int i = 0; i < 4; ++i) {
        #pragma unroll
        for (int r = 0; r < 2; ++r) {
            const int row = mw + i * 16 + r * 8 + (lane >> 2);
            const int b = (m0 + row) / S_;
            const float* de = g_d + b * H_;
            const float* dt = g_d + B_ * H_ + b * H_;
            float pe = 0.f, pt = 0.f;
            #pragma unroll
            for (int j = 0; j < 4; ++j) {
                const int n = n0 + nw + j * 8 + (lane & 3) * 2;
                const float a0 = acc[i][j][r * 2], a1 = acc[i][j][r * 2 + 1];
                const float v0 = __ldg(v_ptr + n), v1 = __ldg(v_ptr + n + 1);
                pe += v0 * tanhf(a0 + __ldg(de + n)) + v1 * tanhf(a1 + __ldg(de + n + 1));
                pt += v0 * tanhf(a0 + __ldg(dt + n)) + v1 * tanhf(a1 + __ldg(dt + n + 1));
            }
            pe += __shfl_xor_sync(0xffffffffu, pe, 1);
            pe += __shfl_xor_sync(0xffffffffu, pe, 2);
            pt += __shfl_xor_sync(0xffffffffu, pt, 1);
            pt += __shfl_xor_sync(0xffffffffu, pt, 2);
            if ((lane & 3) == 0) { redE[row][warp_n] = pe; redT[row][warp_n] = pt; }
        }
    }
    __syncthreads();
    if (tid < 128) {
        const float se = redE[tid][0] + redE[tid][1] + redE[tid][2] + redE[tid][3];
        const float st = redT[tid][0] + redT[tid][1] + redT[tid][2] + redT[tid][3];
        g_fp[half][m0 + tid] = 5.0f * se + st;
    }
}

// ---------------- combine final partials ---------------------------------------
__global__ void combine_kernel(float* __restrict__ out) {
    const int i = blockIdx.x * blockDim.x + threadIdx.x;
    out[i] = g_fp[0][i] + g_fp[1][i];
}

// ---------------- softmax over S (sums the two score partials) -----------------
__global__ void softmax_kernel() {
    const int b = blockIdx.x, which = blockIdx.y;
    const float* s0 = g_sp[0] + which * M_ + b * S_;
    const float* s1 = g_sp[1] + which * M_ + b * S_;
    float* so = g_scores + which * M_ + b * S_;
    const int t = threadIdx.x;
    __shared__ float sred[9];

    float mx = -1e30f;
    for (int i = t; i < S_; i += 256) mx = fmaxf(mx, s0[i] + s1[i]);
    #pragma unroll
    for (int o = 16; o > 0; o >>= 1) mx = fmaxf(mx, __shfl_xor_sync(0xffffffffu, mx, o));
    if ((t & 31) == 0) sred[t >> 5] = mx;
    __syncthreads();
    if (t == 0) {
        float m = sred[0];
        for (int w = 1; w < 8; ++w) m = fmaxf(m, sred[w]);
        sred[8] = m;
    }
    __syncthreads();
    mx = sred[8];

    float sm = 0.f;
    for (int i = t; i < S_; i += 256) sm += expf(s0[i] + s1[i] - mx);
    #pragma unroll
    for (int o = 16; o > 0; o >>= 1) sm += __shfl_xor_sync(0xffffffffu, sm, o);
    if ((t & 31) == 0) sred[t >> 5] = sm;
    __syncthreads();
    if (t == 0) {
        float m = 0.f;
        for (int w = 0; w < 8; ++w) m += sred[w];
        sred[8] = 1.0f / m;
    }
    __syncthreads();
    const float inv = sred[8];
    for (int i = t; i < S_; i += 256) so[i] = expf(s0[i] + s1[i] - mx) * inv;
}

// ---------------- attention contexts: one X pass, both branches ----------------
__global__ void context_kernel(const float* __restrict__ X) {
    const int b = blockIdx.x, chunk = blockIdx.y;  // 10 chunks of 100
    const int t = threadIdx.x;                     // h index
    const float* ae = g_scores + b * S_ + chunk * 100;
    const float* at = g_scores + M_ + b * S_ + chunk * 100;
    const float* x = X + ((size_t)b * S_ + chunk * 100) * H_ + t;
    float ce = 0.f, ct = 0.f;
    #pragma unroll 4
    for (int s = 0; s < 100; ++s) {
        const float xv = x[(size_t)s * H_];
        ce += ae[s] * xv;
        ct += at[s] * xv;
    }
    atomicAdd(&g_ctx[b * H_ + t], ce);
    atomicAdd(&g_ctx[B_ * H_ + b * H_ + t], ct);
}

// ---------------- d vectors -----------------------------------------------------
__global__ void dvec_kernel(const float* __restrict__ Wptr) {
    const int b = blockIdx.x, t = threadIdx.x;
    __shared__ float se[H_], stt[H_];
    se[t] = g_ctx[b * H_ + t];
    stt[t] = g_ctx[B_ * H_ + b * H_ + t];
    __syncthreads();
    float de = g_cs[b * H_ + t], dt = de;
    const float* wr = Wptr + t * (3 * H_) + H_;   // cols [H, 2H)
    #pragma unroll 4
    for (int k = 0; k < H_; ++k) {
        const float w = wr[k];
        de += w * se[k];
        dt += w * stt[k];
    }
    g_d[b * H_ + t] = de;
    g_d[B_ * H_ + b * H_ + t] = dt;
}

// ---------------- launch ---------------------------------------------------------
extern "C" void kernel_launch(void* const* d_in, const int* in_sizes, int n_in,
                              void* d_out, int out_size) {
    const float* x_static = (const float*)d_in[0];
    const float* state_emb = (const float*)d_in[1];
    const float* dec = (const float*)d_in[2];
    const float* tgt = (const float*)d_in[3];
    const float* lasth = (const float*)d_in[4];
    const float* Wih = (const float*)d_in[5];
    const float* Whh = (const float*)d_in[6];
    const float* bih = (const float*)d_in[7];
    const float* bhh = (const float*)d_in[8];
    const float* v_enc = (const float*)d_in[9];
    const float* Wenc = (const float*)d_in[10];
    const float* v_tgt = (const float*)d_in[11];
    const float* Wtgt = (const float*)d_in[12];
    const float* v_ptr = (const float*)d_in[13];
    const float* Wptr = (const float*)d_in[14];

    float* out_probs = (float*)d_out;            // B*S
    float* out_h = (float*)d_out + M_;           // 1*B*H

    // host-side attribute set (idempotent; not a graph node)
    static bool attr_done = false;
    if (!attr_done) {
        cudaFuncSetAttribute(gemm_scores, cudaFuncAttributeMaxDynamicSharedMemorySize, SMTOT);
        cudaFuncSetAttribute(gemm_final, cudaFuncAttributeMaxDynamicSharedMemorySize, SMTOT);
        attr_done = true;
    }

    conv_x<<<16000, 256>>>(x_static);
    conv_w<<<96, 256>>>(Wenc, Wtgt, Wptr);
    zero_ctx<<<(2 * B_ * H_ + 255) / 256, 256>>>();
    gemm_gigh<<<dim3(2, 12, 2), 256>>>(dec, lasth, Wih, Whh);
    gru_elem<<<B_, H_>>>(lasth, bih, bhh, out_h);
    gemm_c<<<dim3(2, 4, 3), 256>>>(tgt, state_emb, Wenc, Wtgt, Wptr);
    gemm_scores<<<dim3(4, 1000), 256, SMTOT>>>(v_enc, v_tgt);
    softmax_kernel<<<dim3(B_, 2), 256>>>();
    context_kernel<<<dim3(B_, 10), H_>>>(x_static);
    dvec_kernel<<<B_, H_>>>(Wptr);
    gemm_final<<<dim3(2, 1000), 256, SMTOT>>>(v_ptr);
    combine_kernel<<<M_ / 256, 256>>>(out_probs);
}

// round 11
// speedup vs baseline: 1.0592x; 1.0592x over previous
#include <cuda_runtime.h>
#include <cuda_bf16.h>
#include <math.h>
#include <stdint.h>

#define B_   128
#define S_   1000
#define H_   256
#define M_   (B_ * S_)   // 128000

// ---------------- scratch (__device__ globals; no allocation allowed) ----------
__device__ float g_ce[B_ * H_];
__device__ float g_ct[B_ * H_];
__device__ float g_cs[B_ * H_];
__device__ float g_gi[B_ * 3 * H_];       // dec @ Wih^T
__device__ float g_gh[B_ * 3 * H_];       // lasth @ Whh^T
__device__ float g_hnew[B_ * H_];
__device__ float g_scores[2 * M_];        // softmaxed attention (enc, tgt)
__device__ float g_sp[2][2 * M_];         // raw score partials per n-half
__device__ float g_fp[2][M_];             // final prob partials per n-half
__device__ float g_ctx[2 * B_ * H_];      // enc ctx, tgt ctx
__device__ float g_d[2 * B_ * H_];        // d_e, d_t
// bf16 hi/lo split of stacked weights [Wenc1; Wtgt1; Wptr1] cols [0,H)
__device__ __nv_bfloat16 g_Whi[768 * H_];
__device__ __nv_bfloat16 g_Wlo[768 * H_];

// =================== mma.sync / ldmatrix / cp.async helpers ====================
__device__ __forceinline__ uint32_t s2u(const void* p) {
    uint32_t a;
    asm("{ .reg .u64 t; cvta.to.shared.u64 t, %1; cvt.u32.u64 %0, t; }" : "=r"(a) : "l"(p));
    return a;
}
__device__ __forceinline__ void ldsm4(uint32_t& r0, uint32_t& r1, uint32_t& r2, uint32_t& r3,
                                      uint32_t addr) {
    asm volatile("ldmatrix.sync.aligned.m8n8.x4.shared.b16 {%0,%1,%2,%3}, [%4];"
                 : "=r"(r0), "=r"(r1), "=r"(r2), "=r"(r3) : "r"(addr));
}
__device__ __forceinline__ void ldsm2(uint32_t& r0, uint32_t& r1, uint32_t addr) {
    asm volatile("ldmatrix.sync.aligned.m8n8.x2.shared.b16 {%0,%1}, [%2];"
                 : "=r"(r0), "=r"(r1) : "r"(addr));
}
__device__ __forceinline__ void mma16816(float& d0, float& d1, float& d2, float& d3,
                                         uint32_t a0, uint32_t a1, uint32_t a2, uint32_t a3,
                                         uint32_t b0, uint32_t b1) {
    asm volatile("mma.sync.aligned.m16n8k16.row.col.f32.bf16.bf16.f32 "
                 "{%0,%1,%2,%3}, {%4,%5,%6,%7}, {%8,%9}, {%0,%1,%2,%3};"
                 : "+f"(d0), "+f"(d1), "+f"(d2), "+f"(d3)
                 : "r"(a0), "r"(a1), "r"(a2), "r"(a3), "r"(b0), "r"(b1));
}
__device__ __forceinline__ void cpa16(uint32_t dst, const void* src) {
    asm volatile("cp.async.cg.shared.global [%0], [%1], 16;" :: "r"(dst), "l"(src));
}
__device__ __forceinline__ void cpa_commit() {
    asm volatile("cp.async.commit_group;" ::: "memory");
}

// ---------------- zero ctx accumulators ----------------------------------------
__global__ void zero_ctx() {
    int i = blockIdx.x * blockDim.x + threadIdx.x;
    if (i < 2 * B_ * H_) g_ctx[i] = 0.0f;
}

// ---------------- prepass: weight fp32 -> bf16 hi/lo ---------------------------
__device__ __forceinline__ void split8(const float* __restrict__ src,
                                       __nv_bfloat16* __restrict__ hi,
                                       __nv_bfloat16* __restrict__ lo) {
    float4 x0 = *(const float4*)src;
    float4 x1 = *(const float4*)(src + 4);
    float v[8] = {x0.x, x0.y, x0.z, x0.w, x1.x, x1.y, x1.z, x1.w};
    __nv_bfloat16 h[8], l[8];
    #pragma unroll
    for (int i = 0; i < 8; ++i) {
        h[i] = __float2bfloat16(v[i]);
        l[i] = __float2bfloat16(v[i] - __bfloat162float(h[i]));
    }
    *(uint4*)hi = *(uint4*)h;
    *(uint4*)lo = *(uint4*)l;
}

__global__ void conv_w(const float* __restrict__ Wenc,
                       const float* __restrict__ Wtgt,
                       const float* __restrict__ Wptr) {
    int g = blockIdx.x * blockDim.x + threadIdx.x;   // 24576 groups
    int row = g >> 5, c8 = g & 31;
    const float* src;
    if (row < 256)      src = Wenc + (size_t)row * (2 * H_) + c8 * 8;
    else if (row < 512) src = Wtgt + (size_t)(row - 256) * (2 * H_) + c8 * 8;
    else                src = Wptr + (size_t)(row - 512) * (3 * H_) + c8 * 8;
    split8(src, g_Whi + (size_t)row * H_ + c8 * 8, g_Wlo + (size_t)row * H_ + c8 * 8);
}

// ---------------- small fp32 GEMM: C[M,N] = A[M,256] @ W[N,256]^T ---------------
__device__ __forceinline__ void gemm64_body(const float* __restrict__ A,
                                            const float* __restrict__ W, int wstride,
                                            float* __restrict__ C, int ldc,
                                            int m0, int n0) {
    __shared__ float As[32][64];
    __shared__ float Bs[32][64];
    const int tid = threadIdx.x;
    const int lm = tid & 63;
    const int lq = tid >> 6;
    const int tn = tid & 15;
    const int tm = tid >> 4;

    float acc[4][4];
    #pragma unroll
    for (int i = 0; i < 4; ++i)
        #pragma unroll
        for (int j = 0; j < 4; ++j) acc[i][j] = 0.f;

    const float* arow = A + (size_t)(m0 + lm) * 256;
    const float* wrow = W + (size_t)(n0 + lm) * wstride;

    for (int kt = 0; kt < 8; ++kt) {
        const int k0 = kt * 32;
        #pragma unroll
        for (int h = 0; h < 2; ++h) {
            const int kk = (lq + h * 4) * 4;
            float4 xa = *(const float4*)(arow + k0 + kk);
            As[kk + 0][lm] = xa.x; As[kk + 1][lm] = xa.y;
            As[kk + 2][lm] = xa.z; As[kk + 3][lm] = xa.w;
            float4 wa = *(const float4*)(wrow + k0 + kk);
            Bs[kk + 0][lm] = wa.x; Bs[kk + 1][lm] = wa.y;
            Bs[kk + 2][lm] = wa.z; Bs[kk + 3][lm] = wa.w;
        }
        __syncthreads();
        #pragma unroll
        for (int k = 0; k < 32; ++k) {
            float4 a = *(const float4*)&As[k][tm * 4];
            float4 b = *(const float4*)&Bs[k][tn * 4];
            acc[0][0] += a.x * b.x; acc[0][1] += a.x * b.y; acc[0][2] += a.x * b.z; acc[0][3] += a.x * b.w;
            acc[1][0] += a.y * b.x; acc[1][1] += a.y * b.y; acc[1][2] += a.y * b.z; acc[1][3] += a.y * b.w;
            acc[2][0] += a.z * b.x; acc[2][1] += a.z * b.y; acc[2][2] += a.z * b.z; acc[2][3] += a.z * b.w;
            acc[3][0] += a.w * b.x; acc[3][1] += a.w * b.y; acc[3][2] += a.w * b.z; acc[3][3] += a.w * b.w;
        }
        __syncthreads();
    }
    #pragma unroll
    for (int i = 0; i < 4; ++i) {
        float4 o = make_float4(acc[i][0], acc[i][1], acc[i][2], acc[i][3]);
        *(float4*)(C + (size_t)(m0 + tm * 4 + i) * ldc + n0 + tn * 4) = o;
    }
}

// merged small GEMMs: z=0: gi, z=1: gh (12 n-tiles); z=2: ct, z=3: cs (4 n-tiles)
__global__ void __launch_bounds__(256) gemm_small(const float* __restrict__ dec,
                                                  const float* __restrict__ lasth,
                                                  const float* __restrict__ tgt,
                                                  const float* __restrict__ semb,
                                                  const float* __restrict__ Wih,
                                                  const float* __restrict__ Whh,
                                                  const float* __restrict__ Wtgt,
                                                  const float* __restrict__ Wptr) {
    const int z = blockIdx.z;
    if (z <= 1) {
        gemm64_body(z == 0 ? dec : lasth, z == 0 ? Wih : Whh, 256,
                    z == 0 ? g_gi : g_gh, 768, blockIdx.x * 64, blockIdx.y * 64);
    } else {
        if (blockIdx.y >= 4) return;
        if (z == 2)
            gemm64_body(tgt, Wtgt + H_, 2 * H_, g_ct, 256, blockIdx.x * 64, blockIdx.y * 64);
        else
            gemm64_body(semb, Wptr + 2 * H_, 3 * H_, g_cs, 256, blockIdx.x * 64, blockIdx.y * 64);
    }
}

__global__ void gru_elem(const float* __restrict__ lasth,
                         const float* __restrict__ bih,
                         const float* __restrict__ bhh,
                         float* __restrict__ out_h) {
    const int b = blockIdx.x, t = threadIdx.x;
    const float gir = g_gi[b * 768 + t] + bih[t];
    const float giz = g_gi[b * 768 + t + H_] + bih[t + H_];
    const float gig = g_gi[b * 768 + t + 2 * H_] + bih[t + 2 * H_];
    const float ghr = g_gh[b * 768 + t] + bhh[t];
    const float ghz = g_gh[b * 768 + t + H_] + bhh[t + H_];
    const float ghg = g_gh[b * 768 + t + 2 * H_] + bhh[t + 2 * H_];
    const float r = 1.0f / (1.0f + expf(-(gir + ghr)));
    const float z = 1.0f / (1.0f + expf(-(giz + ghz)));
    const float n = tanhf(gig + r * ghg);
    const float hn = (1.0f - z) * n + z * lasth[b * H_ + t];
    g_hnew[b * H_ + t] = hn;
    out_h[b * H_ + t] = hn;
}

__global__ void __launch_bounds__(256) gemm_ce(const float* __restrict__ Wenc) {
    gemm64_body(g_hnew, Wenc + H_, 2 * H_, g_ce, 256, blockIdx.x * 64, blockIdx.y * 64);
}

// ---------------- big bf16-split tensor-core GEMM mainloop ---------------------
// CTA: 128(M) x 128(N), K=256 in 8 chunks of 32. cp.async double-buffered B,
// A loaded per-chunk (LDG) with in-register fp32->bf16 hi/lo split.
#define PADB   80                 // smem row stride bytes (64B data + 16 pad)
#define OFF_AH 0
#define OFF_AL 10240
#define OFF_BH 20480
#define OFF_BL 30720
#define STAGEB 40960
#define SMTOT  (2 * STAGEB)       // 81920 bytes dynamic smem

__device__ __forceinline__ void mainloop128(float (&acc)[4][4][4],
                                            const float* __restrict__ X,
                                            int m0, int wrow0,
                                            char* smem, uint32_t sb) {
    const int tid = threadIdx.x;
    const int lane = tid & 31, wid = tid >> 5;
    const int warp_m = wid & 1, warp_n = wid >> 1;

    #pragma unroll
    for (int i = 0; i < 4; ++i)
        #pragma unroll
        for (int j = 0; j < 4; ++j)
            #pragma unroll
            for (int k = 0; k < 4; ++k) acc[i][j][k] = 0.f;

    const int arow = tid >> 3;          // 0..31 (+32p)
    const int ac = tid & 7;             // float4 within row

    const uint32_t aOff = (uint32_t)((warp_m * 64 + (lane & 15)) * PADB + (lane >> 4) * 16);
    const uint32_t bOff = (uint32_t)((warp_n * 32 + (lane & 7)) * PADB + ((lane >> 3) & 1) * 16);

    // ---- prologue: B(0) cp.async ----
    #pragma unroll
    for (int q = 0; q < 2; ++q) {
        const int idx = tid + 256 * q;
        const int row = idx >> 2, c = idx & 3;
        const size_t gsrc = (size_t)(wrow0 + row) * H_ + c * 8;
        const uint32_t d = (uint32_t)(row * PADB + c * 16);
        cpa16(sb + OFF_BH + d, g_Whi + gsrc);
        cpa16(sb + OFF_BL + d, g_Wlo + gsrc);
    }
    cpa_commit();

    for (int kc = 0; kc < 8; ++kc) {
        const uint32_t so = (uint32_t)((kc & 1) * STAGEB);
        const uint32_t sn = (uint32_t)(((kc + 1) & 1) * STAGEB);
        // issue B(kc+1)
        if (kc < 7) {
            const int kn = (kc + 1) * 32;
            #pragma unroll
            for (int q = 0; q < 2; ++q) {
                const int idx = tid + 256 * q;
                const int row = idx >> 2, c = idx & 3;
                const size_t gsrc = (size_t)(wrow0 + row) * H_ + kn + c * 8;
                const uint32_t d = (uint32_t)(row * PADB + c * 16);
                cpa16(sb + sn + OFF_BH + d, g_Whi + gsrc);
                cpa16(sb + sn + OFF_BL + d, g_Wlo + gsrc);
            }
            cpa_commit();
        }
        // load + convert + store A(kc)
        {
            const int k0 = kc * 32;
            #pragma unroll
            for (int p = 0; p < 4; ++p) {
                const float4 x = *(const float4*)(X + (size_t)(m0 + arow + p * 32) * H_ + k0 + ac * 4);
                __nv_bfloat16 h[4], l[4];
                h[0] = __float2bfloat16(x.x); l[0] = __float2bfloat16(x.x - __bfloat162float(h[0]));
                h[1] = __float2bfloat16(x.y); l[1] = __float2bfloat16(x.y - __bfloat162float(h[1]));
                h[2] = __float2bfloat16(x.z); l[2] = __float2bfloat16(x.z - __bfloat162float(h[2]));
                h[3] = __float2bfloat16(x.w); l[3] = __float2bfloat16(x.w - __bfloat162float(h[3]));
                const int d = (arow + p * 32) * PADB + ac * 8;
                *(uint2*)(smem + so + OFF_AH + d) = *(uint2*)h;
                *(uint2*)(smem + so + OFF_AL + d) = *(uint2*)l;
            }
        }
        if (kc < 7) asm volatile("cp.async.wait_group 1;" ::: "memory");
        else        asm volatile("cp.async.wait_group 0;" ::: "memory");
        __syncthreads();
        // ---- 2 x k16 mma on stage ----
        #pragma unroll
        for (int ks = 0; ks < 2; ++ks) {
            const uint32_t kb = ks * 32;
            uint32_t ah[4][4], al[4][4], bh[4][2], bl[4][2];
            #pragma unroll
            for (int i = 0; i < 4; ++i)
                ldsm4(ah[i][0], ah[i][1], ah[i][2], ah[i][3],
                      sb + so + OFF_AH + aOff + i * (16 * PADB) + kb);
            #pragma unroll
            for (int j = 0; j < 4; ++j)
                ldsm2(bh[j][0], bh[j][1], sb + so + OFF_BH + bOff + j * (8 * PADB) + kb);
            #pragma unroll
            for (int i = 0; i < 4; ++i)
                #pragma unroll
                for (int j = 0; j < 4; ++j)
                    mma16816(acc[i][j][0], acc[i][j][1], acc[i][j][2], acc[i][j][3],
                             ah[i][0], ah[i][1], ah[i][2], ah[i][3], bh[j][0], bh[j][1]);
            #pragma unroll
            for (int j = 0; j < 4; ++j)
                ldsm2(bl[j][0], bl[j][1], sb + so + OFF_BL + bOff + j * (8 * PADB) + kb);
            #pragma unroll
            for (int i = 0; i < 4; ++i)
                #pragma unroll
                for (int j = 0; j < 4; ++j)
                    mma16816(acc[i][j][0], acc[i][j][1], acc[i][j][2], acc[i][j][3],
                             ah[i][0], ah[i][1], ah[i][2], ah[i][3], bl[j][0], bl[j][1]);
            #pragma unroll
            for (int i = 0; i < 4; ++i)
                ldsm4(al[i][0], al[i][1], al[i][2], al[i][3],
                      sb + so + OFF_AL + aOff + i * (16 * PADB) + kb);
            #pragma unroll
            for (int i = 0; i < 4; ++i)
                #pragma unroll
                for (int j = 0; j < 4; ++j)
                    mma16816(acc[i][j][0], acc[i][j][1], acc[i][j][2], acc[i][j][3],
                             al[i][0], al[i][1], al[i][2], al[i][3], bh[j][0], bh[j][1]);
        }
        __syncthreads();
    }
}

// ---------------- scores GEMM (enc/tgt) with fused v.tanh reduction ------------
__global__ void __launch_bounds__(256, 2) gemm_scores(const float* __restrict__ X,
                                                      const float* __restrict__ v_enc,
                                                      const float* __restrict__ v_tgt) {
    extern __shared__ char smem[];
    const uint32_t sb = s2u(smem);
    const int tid = threadIdx.x;
    const int lane = tid & 31, wid = tid >> 5;
    const int warp_m = wid & 1, warp_n = wid >> 1;
    const int m0 = blockIdx.y * 128;
    const int grp = blockIdx.x >> 1;           // 0=enc, 1=tgt
    const int half = blockIdx.x & 1;
    const int n0 = half * 128;
    const int wrow0 = grp * 256 + n0;

    float acc[4][4][4];
    mainloop128(acc, X, m0, wrow0, smem, sb);

    float (*red)[4] = (float(*)[4])smem;       // alias stage0 (safe post-sync)
    const int mw = warp_m * 64, nw = warp_n * 32;
    const float* v = (grp == 0) ? v_enc : v_tgt;
    const float* cb = (grp == 0) ? g_ce : g_ct;
    #pragma unroll
    for (int i = 0; i < 4; ++i) {
        #pragma unroll
        for (int r = 0; r < 2; ++r) {
            const int row = mw + i * 16 + r * 8 + (lane >> 2);
            const int b = (m0 + row) / S_;
            const float* cbb = cb + b * H_;
            float p = 0.f;
            #pragma unroll
            for (int j = 0; j < 4; ++j) {
                const int n = n0 + nw + j * 8 + (lane & 3) * 2;
                p += __ldg(v + n) * tanhf(acc[i][j][r * 2] + __ldg(cbb + n));
                p += __ldg(v + n + 1) * tanhf(acc[i][j][r * 2 + 1] + __ldg(cbb + n + 1));
            }
            p += __shfl_xor_sync(0xffffffffu, p, 1);
            p += __shfl_xor_sync(0xffffffffu, p, 2);
            if ((lane & 3) == 0) red[row][warp_n] = p;
        }
    }
    __syncthreads();
    if (tid < 128) {
        const float s = red[tid][0] + red[tid][1] + red[tid][2] + red[tid][3];
        g_sp[half][grp * M_ + m0 + tid] = s;
    }
}

// ---------------- final GEMM (ptr) with fused prob epilogue --------------------
__global__ void __launch_bounds__(256, 2) gemm_final(const float* __restrict__ X,
                                                     const float* __restrict__ v_ptr) {
    extern __shared__ char smem[];
    const uint32_t sb = s2u(smem);
    const int tid = threadIdx.x;
    const int lane = tid & 31, wid = tid >> 5;
    const int warp_m = wid & 1, warp_n = wid >> 1;
    const int m0 = blockIdx.y * 128;
    const int half = blockIdx.x;
    const int n0 = half * 128;
    const int wrow0 = 512 + n0;

    float acc[4][4][4];
    mainloop128(acc, X, m0, wrow0, smem, sb);

    float (*redE)[4] = (float(*)[4])smem;
    float (*redT)[4] = (float(*)[4])(smem + 2048);
    const int mw = warp_m * 64, nw = warp_n * 32;
    #pragma unroll
    for (int i = 0; i < 4; ++i) {
        #pragma unroll
        for (int r = 0; r < 2; ++r) {
            const int row = mw + i * 16 + r * 8 + (lane >> 2);
            const int b = (m0 + row) / S_;
            const float* de = g_d + b * H_;
            const float* dt = g_d + B_ * H_ + b * H_;
            float pe = 0.f, pt = 0.f;
            #pragma unroll
            for (int j = 0; j < 4; ++j) {
                const int n = n0 + nw + j * 8 + (lane & 3) * 2;
                const float a0 = acc[i][j][r * 2], a1 = acc[i][j][r * 2 + 1];
                const float v0 = __ldg(v_ptr + n), v1 = __ldg(v_ptr + n + 1);
                pe += v0 * tanhf(a0 + __ldg(de + n)) + v1 * tanhf(a1 + __ldg(de + n + 1));
                pt += v0 * tanhf(a0 + __ldg(dt + n)) + v1 * tanhf(a1 + __ldg(dt + n + 1));
            }
            pe += __shfl_xor_sync(0xffffffffu, pe, 1);
            pe += __shfl_xor_sync(0xffffffffu, pe, 2);
            pt += __shfl_xor_sync(0xffffffffu, pt, 1);
            pt += __shfl_xor_sync(0xffffffffu, pt, 2);
            if ((lane & 3) == 0) { redE[row][warp_n] = pe; redT[row][warp_n] = pt; }
        }
    }
    __syncthreads();
    if (tid < 128) {
        const float se = redE[tid][0] + redE[tid][1] + redE[tid][2] + redE[tid][3];
        const float st = redT[tid][0] + redT[tid][1] + redT[tid][2] + redT[tid][3];
        g_fp[half][m0 + tid] = 5.0f * se + st;
    }
}

// ---------------- combine final partials ---------------------------------------
__global__ void combine_kernel(float* __restrict__ out) {
    const int i = blockIdx.x * blockDim.x + threadIdx.x;
    out[i] = g_fp[0][i] + g_fp[1][i];
}

// ---------------- softmax over S (sums the two score partials) -----------------
__global__ void softmax_kernel() {
    const int b = blockIdx.x, which = blockIdx.y;
    const float* s0 = g_sp[0] + which * M_ + b * S_;
    const float* s1 = g_sp[1] + which * M_ + b * S_;
    float* so = g_scores + which * M_ + b * S_;
    const int t = threadIdx.x;
    __shared__ float sred[9];

    float mx = -1e30f;
    for (int i = t; i < S_; i += 256) mx = fmaxf(mx, s0[i] + s1[i]);
    #pragma unroll
    for (int o = 16; o > 0; o >>= 1) mx = fmaxf(mx, __shfl_xor_sync(0xffffffffu, mx, o));
    if ((t & 31) == 0) sred[t >> 5] = mx;
    __syncthreads();
    if (t == 0) {
        float m = sred[0];
        for (int w = 1; w < 8; ++w) m = fmaxf(m, sred[w]);
        sred[8] = m;
    }
    __syncthreads();
    mx = sred[8];

    float sm = 0.f;
    for (int i = t; i < S_; i += 256) sm += expf(s0[i] + s1[i] - mx);
    #pragma unroll
    for (int o = 16; o > 0; o >>= 1) sm += __shfl_xor_sync(0xffffffffu, sm, o);
    if ((t & 31) == 0) sred[t >> 5] = sm;
    __syncthreads();
    if (t == 0) {
        float m = 0.f;
        for (int w = 0; w < 8; ++w) m += sred[w];
        sred[8] = 1.0f / m;
    }
    __syncthreads();
    const float inv = sred[8];
    for (int i = t; i < S_; i += 256) so[i] = expf(s0[i] + s1[i] - mx) * inv;
}

// ---------------- attention contexts: one X pass, both branches ----------------
__global__ void context_kernel(const float* __restrict__ X) {
    const int b = blockIdx.x, chunk = blockIdx.y;  // 20 chunks of 50
    const int t = threadIdx.x;                     // h index
    const float* ae = g_scores + b * S_ + chunk * 50;
    const float* at = g_scores + M_ + b * S_ + chunk * 50;
    const float* x = X + ((size_t)b * S_ + chunk * 50) * H_ + t;
    float ce = 0.f, ct = 0.f;
    #pragma unroll 5
    for (int s = 0; s < 50; ++s) {
        const float xv = x[(size_t)s * H_];
        ce += ae[s] * xv;
        ct += at[s] * xv;
    }
    atomicAdd(&g_ctx[b * H_ + t], ce);
    atomicAdd(&g_ctx[B_ * H_ + b * H_ + t], ct);
}

// ---------------- d vectors -----------------------------------------------------
__global__ void dvec_kernel(const float* __restrict__ Wptr) {
    const int b = blockIdx.x, t = threadIdx.x;
    __shared__ float se[H_], stt[H_];
    se[t] = g_ctx[b * H_ + t];
    stt[t] = g_ctx[B_ * H_ + b * H_ + t];
    __syncthreads();
    float de = g_cs[b * H_ + t], dt = de;
    const float* wr = Wptr + t * (3 * H_) + H_;   // cols [H, 2H)
    #pragma unroll 4
    for (int k = 0; k < H_; ++k) {
        const float w = wr[k];
        de += w * se[k];
        dt += w * stt[k];
    }
    g_d[b * H_ + t] = de;
    g_d[B_ * H_ + b * H_ + t] = dt;
}

// ---------------- launch ---------------------------------------------------------
extern "C" void kernel_launch(void* const* d_in, const int* in_sizes, int n_in,
                              void* d_out, int out_size) {
    const float* x_static = (const float*)d_in[0];
    const float* state_emb = (const float*)d_in[1];
    const float* dec = (const float*)d_in[2];
    const float* tgt = (const float*)d_in[3];
    const float* lasth = (const float*)d_in[4];
    const float* Wih = (const float*)d_in[5];
    const float* Whh = (const float*)d_in[6];
    const float* bih = (const float*)d_in[7];
    const float* bhh = (const float*)d_in[8];
    const float* v_enc = (const float*)d_in[9];
    const float* Wenc = (const float*)d_in[10];
    const float* v_tgt = (const float*)d_in[11];
    const float* Wtgt = (const float*)d_in[12];
    const float* v_ptr = (const float*)d_in[13];
    const float* Wptr = (const float*)d_in[14];

    float* out_probs = (float*)d_out;            // B*S
    float* out_h = (float*)d_out + M_;           // 1*B*H

    // host-side attribute set (idempotent; not a graph node)
    static bool attr_done = false;
    if (!attr_done) {
        cudaFuncSetAttribute(gemm_scores, cudaFuncAttributeMaxDynamicSharedMemorySize, SMTOT);
        cudaFuncSetAttribute(gemm_final, cudaFuncAttributeMaxDynamicSharedMemorySize, SMTOT);
        attr_done = true;
    }

    conv_w<<<96, 256>>>(Wenc, Wtgt, Wptr);
    zero_ctx<<<(2 * B_ * H_ + 255) / 256, 256>>>();
    gemm_small<<<dim3(2, 12, 4), 256>>>(dec, lasth, tgt, state_emb, Wih, Whh, Wtgt, Wptr);
    gru_elem<<<B_, H_>>>(lasth, bih, bhh, out_h);
    gemm_ce<<<dim3(2, 4), 256>>>(Wenc);
    gemm_scores<<<dim3(4, 1000), 256, SMTOT>>>(x_static, v_enc, v_tgt);
    softmax_kernel<<<dim3(B_, 2), 256>>>();
    context_kernel<<<dim3(B_, 20), H_>>>(x_static);
    dvec_kernel<<<B_, H_>>>(Wptr);
    gemm_final<<<dim3(2, 1000), 256, SMTOT>>>(x_static, v_ptr);
    combine_kernel<<<M_ / 256, 256>>>(out_probs);
}

// round 12
// speedup vs baseline: 1.6163x; 1.5259x over previous
#include <cuda_runtime.h>
#include <cuda_fp16.h>
#include <math.h>
#include <stdint.h>

#define B_   128
#define S_   1000
#define H_   256
#define M_   (B_ * S_)   // 128000

// ---------------- scratch (__device__ globals; no allocation allowed) ----------
__device__ float g_ce[B_ * H_];
__device__ float g_ct[B_ * H_];
__device__ float g_cs[B_ * H_];
__device__ float g_gi[B_ * 3 * H_];       // dec @ Wih^T
__device__ float g_gh[B_ * 3 * H_];       // lasth @ Whh^T
__device__ float g_hnew[B_ * H_];
__device__ float g_scores[2 * M_];        // softmaxed attention (enc, tgt)
__device__ float g_sp[2][2 * M_];         // raw score partials per n-half
__device__ float g_fp[2][M_];             // final prob partials per n-half
__device__ float g_ctx[2 * B_ * H_];      // enc ctx, tgt ctx
__device__ float g_d[2 * B_ * H_];        // d_e, d_t
// fp16 stacked weights [Wenc1; Wtgt1; Wptr1] cols [0,H)
__device__ __half g_Wh[768 * H_];

// =================== mma.sync / ldmatrix / cp.async helpers ====================
__device__ __forceinline__ uint32_t s2u(const void* p) {
    uint32_t a;
    asm("{ .reg .u64 t; cvta.to.shared.u64 t, %1; cvt.u32.u64 %0, t; }" : "=r"(a) : "l"(p));
    return a;
}
__device__ __forceinline__ void ldsm4(uint32_t& r0, uint32_t& r1, uint32_t& r2, uint32_t& r3,
                                      uint32_t addr) {
    asm volatile("ldmatrix.sync.aligned.m8n8.x4.shared.b16 {%0,%1,%2,%3}, [%4];"
                 : "=r"(r0), "=r"(r1), "=r"(r2), "=r"(r3) : "r"(addr));
}
__device__ __forceinline__ void ldsm2(uint32_t& r0, uint32_t& r1, uint32_t addr) {
    asm volatile("ldmatrix.sync.aligned.m8n8.x2.shared.b16 {%0,%1}, [%2];"
                 : "=r"(r0), "=r"(r1) : "r"(addr));
}
__device__ __forceinline__ void mma16816h(float& d0, float& d1, float& d2, float& d3,
                                          uint32_t a0, uint32_t a1, uint32_t a2, uint32_t a3,
                                          uint32_t b0, uint32_t b1) {
    asm volatile("mma.sync.aligned.m16n8k16.row.col.f32.f16.f16.f32 "
                 "{%0,%1,%2,%3}, {%4,%5,%6,%7}, {%8,%9}, {%0,%1,%2,%3};"
                 : "+f"(d0), "+f"(d1), "+f"(d2), "+f"(d3)
                 : "r"(a0), "r"(a1), "r"(a2), "r"(a3), "r"(b0), "r"(b1));
}
__device__ __forceinline__ void cpa16(uint32_t dst, const void* src) {
    asm volatile("cp.async.cg.shared.global [%0], [%1], 16;" :: "r"(dst), "l"(src));
}
__device__ __forceinline__ void cpa_commit() {
    asm volatile("cp.async.commit_group;" ::: "memory");
}

// ---------------- zero ctx accumulators ----------------------------------------
__global__ void zero_ctx() {
    int i = blockIdx.x * blockDim.x + threadIdx.x;
    if (i < 2 * B_ * H_) g_ctx[i] = 0.0f;
}

// ---------------- prepass: weight fp32 -> fp16 ----------------------------------
__global__ void conv_w(const float* __restrict__ Wenc,
                       const float* __restrict__ Wtgt,
                       const float* __restrict__ Wptr) {
    int g = blockIdx.x * blockDim.x + threadIdx.x;   // 24576 groups of 8
    int row = g >> 5, c8 = g & 31;
    const float* src;
    if (row < 256)      src = Wenc + (size_t)row * (2 * H_) + c8 * 8;
    else if (row < 512) src = Wtgt + (size_t)(row - 256) * (2 * H_) + c8 * 8;
    else                src = Wptr + (size_t)(row - 512) * (3 * H_) + c8 * 8;
    float4 x0 = *(const float4*)src;
    float4 x1 = *(const float4*)(src + 4);
    __half h[8];
    h[0] = __float2half_rn(x0.x); h[1] = __float2half_rn(x0.y);
    h[2] = __float2half_rn(x0.z); h[3] = __float2half_rn(x0.w);
    h[4] = __float2half_rn(x1.x); h[5] = __float2half_rn(x1.y);
    h[6] = __float2half_rn(x1.z); h[7] = __float2half_rn(x1.w);
    *(uint4*)(g_Wh + (size_t)row * H_ + c8 * 8) = *(uint4*)h;
}

// ---------------- small fp32 GEMM: C[M,N] = A[M,256] @ W[N,256]^T ---------------
__device__ __forceinline__ void gemm64_body(const float* __restrict__ A,
                                            const float* __restrict__ W, int wstride,
                                            float* __restrict__ C, int ldc,
                                            int m0, int n0) {
    __shared__ float As[32][64];
    __shared__ float Bs[32][64];
    const int tid = threadIdx.x;
    const int lm = tid & 63;
    const int lq = tid >> 6;
    const int tn = tid & 15;
    const int tm = tid >> 4;

    float acc[4][4];
    #pragma unroll
    for (int i = 0; i < 4; ++i)
        #pragma unroll
        for (int j = 0; j < 4; ++j) acc[i][j] = 0.f;

    const float* arow = A + (size_t)(m0 + lm) * 256;
    const float* wrow = W + (size_t)(n0 + lm) * wstride;

    for (int kt = 0; kt < 8; ++kt) {
        const int k0 = kt * 32;
        #pragma unroll
        for (int h = 0; h < 2; ++h) {
            const int kk = (lq + h * 4) * 4;
            float4 xa = *(const float4*)(arow + k0 + kk);
            As[kk + 0][lm] = xa.x; As[kk + 1][lm] = xa.y;
            As[kk + 2][lm] = xa.z; As[kk + 3][lm] = xa.w;
            float4 wa = *(const float4*)(wrow + k0 + kk);
            Bs[kk + 0][lm] = wa.x; Bs[kk + 1][lm] = wa.y;
            Bs[kk + 2][lm] = wa.z; Bs[kk + 3][lm] = wa.w;
        }
        __syncthreads();
        #pragma unroll
        for (int k = 0; k < 32; ++k) {
            float4 a = *(const float4*)&As[k][tm * 4];
            float4 b = *(const float4*)&Bs[k][tn * 4];
            acc[0][0] += a.x * b.x; acc[0][1] += a.x * b.y; acc[0][2] += a.x * b.z; acc[0][3] += a.x * b.w;
            acc[1][0] += a.y * b.x; acc[1][1] += a.y * b.y; acc[1][2] += a.y * b.z; acc[1][3] += a.y * b.w;
            acc[2][0] += a.z * b.x; acc[2][1] += a.z * b.y; acc[2][2] += a.z * b.z; acc[2][3] += a.z * b.w;
            acc[3][0] += a.w * b.x; acc[3][1] += a.w * b.y; acc[3][2] += a.w * b.z; acc[3][3] += a.w * b.w;
        }
        __syncthreads();
    }
    #pragma unroll
    for (int i = 0; i < 4; ++i) {
        float4 o = make_float4(acc[i][0], acc[i][1], acc[i][2], acc[i][3]);
        *(float4*)(C + (size_t)(m0 + tm * 4 + i) * ldc + n0 + tn * 4) = o;
    }
}

// merged small GEMMs: z=0: gi, z=1: gh (12 n-tiles); z=2: ct, z=3: cs (4 n-tiles)
__global__ void __launch_bounds__(256) gemm_small(const float* __restrict__ dec,
                                                  const float* __restrict__ lasth,
                                                  const float* __restrict__ tgt,
                                                  const float* __restrict__ semb,
                                                  const float* __restrict__ Wih,
                                                  const float* __restrict__ Whh,
                                                  const float* __restrict__ Wtgt,
                                                  const float* __restrict__ Wptr) {
    const int z = blockIdx.z;
    if (z <= 1) {
        gemm64_body(z == 0 ? dec : lasth, z == 0 ? Wih : Whh, 256,
                    z == 0 ? g_gi : g_gh, 768, blockIdx.x * 64, blockIdx.y * 64);
    } else {
        if (blockIdx.y >= 4) return;
        if (z == 2)
            gemm64_body(tgt, Wtgt + H_, 2 * H_, g_ct, 256, blockIdx.x * 64, blockIdx.y * 64);
        else
            gemm64_body(semb, Wptr + 2 * H_, 3 * H_, g_cs, 256, blockIdx.x * 64, blockIdx.y * 64);
    }
}

__global__ void gru_elem(const float* __restrict__ lasth,
                         const float* __restrict__ bih,
                         const float* __restrict__ bhh,
                         float* __restrict__ out_h) {
    const int b = blockIdx.x, t = threadIdx.x;
    const float gir = g_gi[b * 768 + t] + bih[t];
    const float giz = g_gi[b * 768 + t + H_] + bih[t + H_];
    const float gig = g_gi[b * 768 + t + 2 * H_] + bih[t + 2 * H_];
    const float ghr = g_gh[b * 768 + t] + bhh[t];
    const float ghz = g_gh[b * 768 + t + H_] + bhh[t + H_];
    const float ghg = g_gh[b * 768 + t + 2 * H_] + bhh[t + 2 * H_];
    const float r = 1.0f / (1.0f + expf(-(gir + ghr)));
    const float z = 1.0f / (1.0f + expf(-(giz + ghz)));
    const float n = tanhf(gig + r * ghg);
    const float hn = (1.0f - z) * n + z * lasth[b * H_ + t];
    g_hnew[b * H_ + t] = hn;
    out_h[b * H_ + t] = hn;
}

__global__ void __launch_bounds__(256) gemm_ce(const float* __restrict__ Wenc) {
    gemm64_body(g_hnew, Wenc + H_, 2 * H_, g_ce, 256, blockIdx.x * 64, blockIdx.y * 64);
}

// ---------------- big fp16 tensor-core GEMM mainloop ----------------------------
// CTA: 128(M) x 128(N), K=256 in 8 chunks of 32, single-pass fp16 mma.
// B via double-buffered cp.async from pre-converted fp16 weights; A loaded as
// fp32 per-chunk and converted in-register to fp16.
#define PADB   80                 // smem row stride bytes (64B data + 16 pad)
#define OFF_A  0
#define OFF_B  10240
#define STAGEB 20480
#define SMTOT  (2 * STAGEB)       // 40960 bytes dynamic smem (< 48KB default)

__device__ __forceinline__ void mainloop128(float (&acc)[4][4][4],
                                            const float* __restrict__ X,
                                            int m0, int wrow0,
                                            char* smem, uint32_t sb) {
    const int tid = threadIdx.x;
    const int lane = tid & 31, wid = tid >> 5;
    const int warp_m = wid & 1, warp_n = wid >> 1;

    #pragma unroll
    for (int i = 0; i < 4; ++i)
        #pragma unroll
        for (int j = 0; j < 4; ++j)
            #pragma unroll
            for (int k = 0; k < 4; ++k) acc[i][j][k] = 0.f;

    const int arow = tid >> 3;          // 0..31 (+32p)
    const int ac = tid & 7;             // float4 within row

    const uint32_t aOff = (uint32_t)((warp_m * 64 + (lane & 15)) * PADB + (lane >> 4) * 16);
    const uint32_t bOff = (uint32_t)((warp_n * 32 + (lane & 7)) * PADB + ((lane >> 3) & 1) * 16);

    // ---- prologue: B(0) cp.async ----
    #pragma unroll
    for (int q = 0; q < 2; ++q) {
        const int idx = tid + 256 * q;
        const int row = idx >> 2, c = idx & 3;
        cpa16(sb + OFF_B + (uint32_t)(row * PADB + c * 16),
              g_Wh + (size_t)(wrow0 + row) * H_ + c * 8);
    }
    cpa_commit();

    for (int kc = 0; kc < 8; ++kc) {
        const uint32_t so = (uint32_t)((kc & 1) * STAGEB);
        const uint32_t sn = (uint32_t)(((kc + 1) & 1) * STAGEB);
        // issue B(kc+1)
        if (kc < 7) {
            const int kn = (kc + 1) * 32;
            #pragma unroll
            for (int q = 0; q < 2; ++q) {
                const int idx = tid + 256 * q;
                const int row = idx >> 2, c = idx & 3;
                cpa16(sb + sn + OFF_B + (uint32_t)(row * PADB + c * 16),
                      g_Wh + (size_t)(wrow0 + row) * H_ + kn + c * 8);
            }
            cpa_commit();
        }
        // load + convert + store A(kc)
        {
            const int k0 = kc * 32;
            #pragma unroll
            for (int p = 0; p < 4; ++p) {
                const float4 x = *(const float4*)(X + (size_t)(m0 + arow + p * 32) * H_ + k0 + ac * 4);
                __half h[4];
                h[0] = __float2half_rn(x.x); h[1] = __float2half_rn(x.y);
                h[2] = __float2half_rn(x.z); h[3] = __float2half_rn(x.w);
                *(uint2*)(smem + so + OFF_A + (arow + p * 32) * PADB + ac * 8) = *(uint2*)h;
            }
        }
        if (kc < 7) asm volatile("cp.async.wait_group 1;" ::: "memory");
        else        asm volatile("cp.async.wait_group 0;" ::: "memory");
        __syncthreads();
        // ---- 2 x k16 mma on stage ----
        #pragma unroll
        for (int ks = 0; ks < 2; ++ks) {
            const uint32_t kb = ks * 32;
            uint32_t a[4][4], b[4][2];
            #pragma unroll
            for (int i = 0; i < 4; ++i)
                ldsm4(a[i][0], a[i][1], a[i][2], a[i][3],
                      sb + so + OFF_A + aOff + i * (16 * PADB) + kb);
            #pragma unroll
            for (int j = 0; j < 4; ++j)
                ldsm2(b[j][0], b[j][1], sb + so + OFF_B + bOff + j * (8 * PADB) + kb);
            #pragma unroll
            for (int i = 0; i < 4; ++i)
                #pragma unroll
                for (int j = 0; j < 4; ++j)
                    mma16816h(acc[i][j][0], acc[i][j][1], acc[i][j][2], acc[i][j][3],
                              a[i][0], a[i][1], a[i][2], a[i][3], b[j][0], b[j][1]);
        }
        __syncthreads();
    }
}

// ---------------- scores GEMM (enc/tgt) with fused v.tanh reduction ------------
__global__ void __launch_bounds__(256, 2) gemm_scores(const float* __restrict__ X,
                                                      const float* __restrict__ v_enc,
                                                      const float* __restrict__ v_tgt) {
    extern __shared__ char smem[];
    const uint32_t sb = s2u(smem);
    const int tid = threadIdx.x;
    const int lane = tid & 31, wid = tid >> 5;
    const int warp_m = wid & 1, warp_n = wid >> 1;
    const int m0 = blockIdx.y * 128;
    const int grp = blockIdx.x >> 1;           // 0=enc, 1=tgt
    const int half = blockIdx.x & 1;
    const int n0 = half * 128;
    const int wrow0 = grp * 256 + n0;

    float acc[4][4][4];
    mainloop128(acc, X, m0, wrow0, smem, sb);

    float (*red)[4] = (float(*)[4])smem;       // alias stage0 (safe post-sync)
    const int mw = warp_m * 64, nw = warp_n * 32;
    const float* v = (grp == 0) ? v_enc : v_tgt;
    const float* cb = (grp == 0) ? g_ce : g_ct;
    #pragma unroll
    for (int i = 0; i < 4; ++i) {
        #pragma unroll
        for (int r = 0; r < 2; ++r) {
            const int row = mw + i * 16 + r * 8 + (lane >> 2);
            const int b = (m0 + row) / S_;
            const float* cbb = cb + b * H_;
            float p = 0.f;
            #pragma unroll
            for (int j = 0; j < 4; ++j) {
                const int n = n0 + nw + j * 8 + (lane & 3) * 2;
                p += __ldg(v + n) * tanhf(acc[i][j][r * 2] + __ldg(cbb + n));
                p += __ldg(v + n + 1) * tanhf(acc[i][j][r * 2 + 1] + __ldg(cbb + n + 1));
            }
            p += __shfl_xor_sync(0xffffffffu, p, 1);
            p += __shfl_xor_sync(0xffffffffu, p, 2);
            if ((lane & 3) == 0) red[row][warp_n] = p;
        }
    }
    __syncthreads();
    if (tid < 128) {
        const float s = red[tid][0] + red[tid][1] + red[tid][2] + red[tid][3];
        g_sp[half][grp * M_ + m0 + tid] = s;
    }
}

// ---------------- final GEMM (ptr) with fused prob epilogue --------------------
__global__ void __launch_bounds__(256, 2) gemm_final(const float* __restrict__ X,
                                                     const float* __restrict__ v_ptr) {
    extern __shared__ char smem[];
    const uint32_t sb = s2u(smem);
    const int tid = threadIdx.x;
    const int lane = tid & 31, wid = tid >> 5;
    const int warp_m = wid & 1, warp_n = wid >> 1;
    const int m0 = blockIdx.y * 128;
    const int half = blockIdx.x;
    const int n0 = half * 128;
    const int wrow0 = 512 + n0;

    float acc[4][4][4];
    mainloop128(acc, X, m0, wrow0, smem, sb);

    float (*redE)[4] = (float(*)[4])smem;
    float (*redT)[4] = (float(*)[4])(smem + 2048);
    const int mw = warp_m * 64, nw = warp_n * 32;
    #pragma unroll
    for (int i = 0; i < 4; ++i) {
        #pragma unroll
        for (int r = 0; r < 2; ++r) {
            const int row = mw + i * 16 + r * 8 + (lane >> 2);
            const int b = (m0 + row) / S_;
            const float* de = g_d + b * H_;
            const float* dt = g_d + B_ * H_ + b * H_;
            float pe = 0.f, pt = 0.f;
            #pragma unroll
            for (int j = 0; j < 4; ++j) {
                const int n = n0 + nw + j * 8 + (lane & 3) * 2;
                const float a0 = acc[i][j][r * 2], a1 = acc[i][j][r * 2 + 1];
                const float v0 = __ldg(v_ptr + n), v1 = __ldg(v_ptr + n + 1);
                pe += v0 * tanhf(a0 + __ldg(de + n)) + v1 * tanhf(a1 + __ldg(de + n + 1));
                pt += v0 * tanhf(a0 + __ldg(dt + n)) + v1 * tanhf(a1 + __ldg(dt + n + 1));
            }
            pe += __shfl_xor_sync(0xffffffffu, pe, 1);
            pe += __shfl_xor_sync(0xffffffffu, pe, 2);
            pt += __shfl_xor_sync(0xffffffffu, pt, 1);
            pt += __shfl_xor_sync(0xffffffffu, pt, 2);
            if ((lane & 3) == 0) { redE[row][warp_n] = pe; redT[row][warp_n] = pt; }
        }
    }
    __syncthreads();
    if (tid < 128) {
        const float se = redE[tid][0] + redE[tid][1] + redE[tid][2] + redE[tid][3];
        const float st = redT[tid][0] + redT[tid][1] + redT[tid][2] + redT[tid][3];
        g_fp[half][m0 + tid] = 5.0f * se + st;
    }
}

// ---------------- combine final partials ---------------------------------------
__global__ void combine_kernel(float* __restrict__ out) {
    const int i = blockIdx.x * blockDim.x + threadIdx.x;
    out[i] = g_fp[0][i] + g_fp[1][i];
}

// ---------------- softmax over S (sums the two score partials) -----------------
__global__ void softmax_kernel() {
    const int b = blockIdx.x, which = blockIdx.y;
    const float* s0 = g_sp[0] + which * M_ + b * S_;
    const float* s1 = g_sp[1] + which * M_ + b * S_;
    float* so = g_scores + which * M_ + b * S_;
    const int t = threadIdx.x;
    __shared__ float sred[9];

    float mx = -1e30f;
    for (int i = t; i < S_; i += 256) mx = fmaxf(mx, s0[i] + s1[i]);
    #pragma unroll
    for (int o = 16; o > 0; o >>= 1) mx = fmaxf(mx, __shfl_xor_sync(0xffffffffu, mx, o));
    if ((t & 31) == 0) sred[t >> 5] = mx;
    __syncthreads();
    if (t == 0) {
        float m = sred[0];
        for (int w = 1; w < 8; ++w) m = fmaxf(m, sred[w]);
        sred[8] = m;
    }
    __syncthreads();
    mx = sred[8];

    float sm = 0.f;
    for (int i = t; i < S_; i += 256) sm += expf(s0[i] + s1[i] - mx);
    #pragma unroll
    for (int o = 16; o > 0; o >>= 1) sm += __shfl_xor_sync(0xffffffffu, sm, o);
    if ((t & 31) == 0) sred[t >> 5] = sm;
    __syncthreads();
    if (t == 0) {
        float m = 0.f;
        for (int w = 0; w < 8; ++w) m += sred[w];
        sred[8] = 1.0f / m;
    }
    __syncthreads();
    const float inv = sred[8];
    for (int i = t; i < S_; i += 256) so[i] = expf(s0[i] + s1[i] - mx) * inv;
}

// ---------------- attention contexts: one X pass, both branches ----------------
__global__ void context_kernel(const float* __restrict__ X) {
    const int b = blockIdx.x, chunk = blockIdx.y;  // 20 chunks of 50
    const int t = threadIdx.x;                     // h index
    const float* ae = g_scores + b * S_ + chunk * 50;
    const float* at = g_scores + M_ + b * S_ + chunk * 50;
    const float* x = X + ((size_t)b * S_ + chunk * 50) * H_ + t;
    float ce = 0.f, ct = 0.f;
    #pragma unroll 5
    for (int s = 0; s < 50; ++s) {
        const float xv = x[(size_t)s * H_];
        ce += ae[s] * xv;
        ct += at[s] * xv;
    }
    atomicAdd(&g_ctx[b * H_ + t], ce);
    atomicAdd(&g_ctx[B_ * H_ + b * H_ + t], ct);
}

// ---------------- d vectors -----------------------------------------------------
__global__ void dvec_kernel(const float* __restrict__ Wptr) {
    const int b = blockIdx.x, t = threadIdx.x;
    __shared__ float se[H_], stt[H_];
    se[t] = g_ctx[b * H_ + t];
    stt[t] = g_ctx[B_ * H_ + b * H_ + t];
    __syncthreads();
    float de = g_cs[b * H_ + t], dt = de;
    const float* wr = Wptr + t * (3 * H_) + H_;   // cols [H, 2H)
    #pragma unroll 4
    for (int k = 0; k < H_; ++k) {
        const float w = wr[k];
        de += w * se[k];
        dt += w * stt[k];
    }
    g_d[b * H_ + t] = de;
    g_d[B_ * H_ + b * H_ + t] = dt;
}

// ---------------- launch ---------------------------------------------------------
extern "C" void kernel_launch(void* const* d_in, const int* in_sizes, int n_in,
                              void* d_out, int out_size) {
    const float* x_static = (const float*)d_in[0];
    const float* state_emb = (const float*)d_in[1];
    const float* dec = (const float*)d_in[2];
    const float* tgt = (const float*)d_in[3];
    const float* lasth = (const float*)d_in[4];
    const float* Wih = (const float*)d_in[5];
    const float* Whh = (const float*)d_in[6];
    const float* bih = (const float*)d_in[7];
    const float* bhh = (const float*)d_in[8];
    const float* v_enc = (const float*)d_in[9];
    const float* Wenc = (const float*)d_in[10];
    const float* v_tgt = (const float*)d_in[11];
    const float* Wtgt = (const float*)d_in[12];
    const float* v_ptr = (const float*)d_in[13];
    const float* Wptr = (const float*)d_in[14];

    float* out_probs = (float*)d_out;            // B*S
    float* out_h = (float*)d_out + M_;           // 1*B*H

    conv_w<<<96, 256>>>(Wenc, Wtgt, Wptr);
    zero_ctx<<<(2 * B_ * H_ + 255) / 256, 256>>>();
    gemm_small<<<dim3(2, 12, 4), 256>>>(dec, lasth, tgt, state_emb, Wih, Whh, Wtgt, Wptr);
    gru_elem<<<B_, H_>>>(lasth, bih, bhh, out_h);
    gemm_ce<<<dim3(2, 4), 256>>>(Wenc);
    gemm_scores<<<dim3(4, 1000), 256, SMTOT>>>(x_static, v_enc, v_tgt);
    softmax_kernel<<<dim3(B_, 2), 256>>>();
    context_kernel<<<dim3(B_, 20), H_>>>(x_static);
    dvec_kernel<<<B_, H_>>>(Wptr);
    gemm_final<<<dim3(2, 1000), 256, SMTOT>>>(x_static, v_ptr);
    combine_kernel<<<M_ / 256, 256>>>(out_probs);
}